// round 10
// baseline (speedup 1.0000x reference)
#include <cuda_runtime.h>
#include <cuda_bf16.h>
#include <cstdint>

// Stickbreaking attention via mma.sync (HMMA) bf16-split. B=2 H=16 S=1024 D=64.
// Linear domain: z = sigmoid(x), beta = 1-z; w[i,k] = z_ik*beta_ik*prod_{k<j<=i} beta_ij.
// Key blocks streamed descending with multiplicative carry P per row.
// Q tiles resident in smem (re-LDSM'd per pass) -> 3 CTAs/SM.

#define SEQ 1024
#define DH 64
#define BQ 64
#define BK 64
#define THREADS 128
#define NQB (SEQ / BQ)
#define FULL 0xffffffffu

#define KH_O 0
#define KL_O 8192
#define VH_O 16384
#define VL_O 24576
#define QH_O 32768
#define QL_O 40960
#define SM_TOTAL 49152

__device__ __forceinline__ uint32_t smem_u32(const void* p) {
    uint32_t a;
    asm("{ .reg .u64 t; cvta.to.shared.u64 t, %1; cvt.u32.u64 %0, t; }" : "=r"(a) : "l"(p));
    return a;
}
__device__ __forceinline__ float ex2f(float x) {
    float r; asm("ex2.approx.f32 %0, %1;" : "=f"(r) : "f"(x)); return r;
}
__device__ __forceinline__ float rcpf(float x) {
    float r; asm("rcp.approx.f32 %0, %1;" : "=f"(r) : "f"(x)); return r;
}

#define MMA(d, a, b0, b1) \
    asm volatile("mma.sync.aligned.m16n8k16.row.col.f32.bf16.bf16.f32 " \
        "{%0,%1,%2,%3}, {%4,%5,%6,%7}, {%8,%9}, {%0,%1,%2,%3};" \
        : "+f"((d)[0]), "+f"((d)[1]), "+f"((d)[2]), "+f"((d)[3]) \
        : "r"((a)[0]), "r"((a)[1]), "r"((a)[2]), "r"((a)[3]), "r"(b0), "r"(b1))

#define LDSM4(r, addr) \
    asm volatile("ldmatrix.sync.aligned.m8n8.x4.shared.b16 {%0,%1,%2,%3}, [%4];" \
        : "=r"((r)[0]), "=r"((r)[1]), "=r"((r)[2]), "=r"((r)[3]) : "r"(addr))

#define LDSM4T(r, addr) \
    asm volatile("ldmatrix.sync.aligned.m8n8.x4.trans.shared.b16 {%0,%1,%2,%3}, [%4];" \
        : "=r"((r)[0]), "=r"((r)[1]), "=r"((r)[2]), "=r"((r)[3]) : "r"(addr))

__device__ __forceinline__ uint32_t pack2(__nv_bfloat16 lo, __nv_bfloat16 hi) {
    __nv_bfloat162 t(lo, hi);
    return *reinterpret_cast<uint32_t*>(&t);
}
__device__ __forceinline__ void split2(float x, __nv_bfloat16& h, __nv_bfloat16& l) {
    h = __float2bfloat16_rn(x);
    l = __float2bfloat16_rn(x - __bfloat162float(h));
}

// convert one 64x64 fp32 block (regs) -> bf16 hi/lo tiles at hiOff/loOff
__device__ __forceinline__ void conv_blk(char* smem, uint32_t hiOff, uint32_t loOff,
                                         const float4* r, int tid) {
    #pragma unroll
    for (int i = 0; i < 8; i++) {
        int f = i * THREADS + tid;
        int row = f >> 4, c4 = f & 15;
        uint32_t off = (uint32_t)(row * 128 + (((c4 >> 1) ^ (row & 7)) << 4) + (c4 & 1) * 8);
        __nv_bfloat16 h0, h1, h2, h3, l0, l1, l2, l3;
        split2(r[i].x, h0, l0); split2(r[i].y, h1, l1);
        split2(r[i].z, h2, l2); split2(r[i].w, h3, l3);
        *(uint2*)(smem + hiOff + off) = make_uint2(pack2(h0, h1), pack2(h2, h3));
        *(uint2*)(smem + loOff + off) = make_uint2(pack2(l0, l1), pack2(l2, l3));
    }
}

__global__ __launch_bounds__(THREADS, 3)
void sb_mma(const float* __restrict__ q, const float* __restrict__ k,
            const float* __restrict__ v, float* __restrict__ out) {
    extern __shared__ __align__(16) char smem[];
    const uint32_t sb = smem_u32(smem);
    const int tid = threadIdx.x;
    const int lane = tid & 31, warp = tid >> 5;
    const int q4 = lane & 3;                     // quad col idx
    const int sel = lane >> 3, rr = lane & 7;    // ldmatrix select / row

    const int idx = blockIdx.x;
    const int qb = (NQB - 1) - (idx >> 5);       // heaviest q-tiles first
    const int bh = idx & 31;
    const int qbase = qb * BQ;

    const float* qg = q + (size_t)bh * SEQ * DH;
    const float* kg = k + (size_t)bh * SEQ * DH;
    const float* vg = v + (size_t)bh * SEQ * DH;
    float* og = out + (size_t)bh * SEQ * DH;

    // ---- stage Q tile (bf16 hi/lo) resident in QH/QL ----
    {
        float4 qr[8];
        const float4* gq = (const float4*)(qg + (size_t)qbase * DH);
        #pragma unroll
        for (int i = 0; i < 8; i++) qr[i] = gq[i * THREADS + tid];
        conv_blk(smem, QH_O, QL_O, qr, tid);
    }

    // ---- preload first K block into registers ----
    float4 kr[8];
    {
        const float4* gk = (const float4*)(kg + (size_t)(qb * BK) * DH);
        #pragma unroll
        for (int i = 0; i < 8; i++) kr[i] = gk[i * THREADS + tid];
    }
    __syncthreads();   // Q resident before QK reads it

    float o[8][4];
    #pragma unroll
    for (int nt = 0; nt < 8; nt++) { o[nt][0] = o[nt][1] = o[nt][2] = o[nt][3] = 0.f; }
    float P0 = 1.f, P1 = 1.f;                    // multiplicative carries
    const int wr0 = qbase + warp * 16 + (lane >> 2);
    const float SC = 0.18033688f;                // 0.125 * log2(e)
    const int qrow = warp * 16 + (sel & 1) * 8 + rr;

    #pragma unroll 1
    for (int kb = qb; kb >= 0; --kb) {
        const int kbase = kb * BK;

        // -- convert current K block (kr now consumed) --
        conv_blk(smem, KH_O, KL_O, kr, tid);
        __syncthreads();   // K visible; prev PV reads of V done (all passed prior barrier)

        // -- issue V LDG (current block) and next K LDG: covered by QK+scan --
        float4 vr[8];
        {
            const float4* gv = (const float4*)(vg + (size_t)kbase * DH);
            #pragma unroll
            for (int i = 0; i < 8; i++) vr[i] = gv[i * THREADS + tid];
        }
        if (kb > 0) {
            const float4* gk = (const float4*)(kg + (size_t)(kbase - BK) * DH);
            #pragma unroll
            for (int i = 0; i < 8; i++) kr[i] = gk[i * THREADS + tid];
        }

        // ---- QK^T: D[16 rows x 64 keys], 3 split passes; Q via LDSM per pass ----
        float d[8][4];
        #pragma unroll
        for (int nt = 0; nt < 8; nt++) { d[nt][0] = d[nt][1] = d[nt][2] = d[nt][3] = 0.f; }

        #pragma unroll
        for (int kc = 0; kc < 4; kc++) {
            const int chunk = 2 * kc + (sel >> 1);
            const int keyl = (sel >> 1) * 8 + rr;
            const int kchunk = 2 * kc + (sel & 1);
            uint32_t qa = sb + (uint32_t)(qrow * 128 + ((chunk ^ rr) << 4));
            uint32_t qhf[4], qlf[4], kf[16];
            LDSM4(qhf, qa + QH_O);
            LDSM4(qlf, qa + QL_O);
            #pragma unroll
            for (int p = 0; p < 4; p++) {
                uint32_t a = sb + KH_O + (uint32_t)((p * 16 + keyl) * 128 + ((kchunk ^ rr) << 4));
                LDSM4(&kf[p * 4], a);
            }
            #pragma unroll
            for (int nt = 0; nt < 8; nt++) MMA(d[nt], qhf, kf[nt * 2], kf[nt * 2 + 1]);
            #pragma unroll
            for (int nt = 0; nt < 8; nt++) MMA(d[nt], qlf, kf[nt * 2], kf[nt * 2 + 1]);
            #pragma unroll
            for (int p = 0; p < 4; p++) {
                uint32_t a = sb + KL_O + (uint32_t)((p * 16 + keyl) * 128 + ((kchunk ^ rr) << 4));
                LDSM4(&kf[p * 4], a);
            }
            #pragma unroll
            for (int nt = 0; nt < 8; nt++) MMA(d[nt], qhf, kf[nt * 2], kf[nt * 2 + 1]);
        }

        // ---- stickbreaking scan: linear domain, suffix product over quad ----
        uint32_t wha[4][4], wla[4][4];
        const bool diag = (kb == qb);
        #pragma unroll
        for (int nt = 7; nt >= 0; --nt) {
            const int keyA = kbase + nt * 8 + 2 * q4;
            #pragma unroll
            for (int rs = 0; rs < 2; rs++) {
                float x2a = d[nt][rs * 2 + 0] * SC;
                float x2b = d[nt][rs * 2 + 1] * SC;
                float ta = ex2f(-x2a), tb = ex2f(-x2b);
                float za = rcpf(1.f + ta), zb = rcpf(1.f + tb);
                float ba = 1.f - za, bb = 1.f - zb;
                if (diag) {
                    const int rowg = wr0 + rs * 8;
                    if (keyA > rowg)     { za = 0.f; ba = 1.f; }
                    if (keyA + 1 > rowg) { zb = 0.f; bb = 1.f; }
                }
                float pp = ba * bb;
                float u = pp;                               // inclusive suffix product
                float t1 = __shfl_down_sync(FULL, u, 1, 4);
                u = (q4 < 3) ? u * t1 : u;
                float t2 = __shfl_down_sync(FULL, u, 2, 4);
                u = (q4 < 2) ? u * t2 : u;
                float ue = __shfl_down_sync(FULL, u, 1, 4); // exclusive (lanes above)
                ue = (q4 < 3) ? ue : 1.f;
                float tot = __shfl_sync(FULL, u, 0, 4);
                float& P = rs ? P1 : P0;
                float R  = P * ue;                          // betas of all higher keys
                float Rb = bb * R;
                float wb = zb * Rb;
                float Ra = ba * Rb;
                float wa = za * Ra;
                P *= tot;
                __nv_bfloat16 ah, al, bh2, bl2;
                split2(wa, ah, al); split2(wb, bh2, bl2);
                wha[nt >> 1][(nt & 1) * 2 + rs] = pack2(ah, bh2);
                wla[nt >> 1][(nt & 1) * 2 + rs] = pack2(al, bl2);
            }
        }

        // -- convert V block (loads have landed during QK+scan) --
        conv_blk(smem, VH_O, VL_O, vr, tid);
        __syncthreads();   // V visible to all warps

        // ---- PV: O += W * V (V via ldmatrix.trans), 3 split passes ----
        #pragma unroll
        for (int kc = 0; kc < 4; kc++) {
            uint32_t vf[16];
            const int keyv = kc * 16 + (sel & 1) * 8 + rr;
            #pragma unroll
            for (int p = 0; p < 4; p++) {
                int chunk = 2 * p + (sel >> 1);
                uint32_t a = sb + VH_O + (uint32_t)(keyv * 128 + ((chunk ^ rr) << 4));
                LDSM4T(&vf[p * 4], a);
            }
            #pragma unroll
            for (int nt = 0; nt < 8; nt++) MMA(o[nt], wha[kc], vf[nt * 2], vf[nt * 2 + 1]);
            #pragma unroll
            for (int nt = 0; nt < 8; nt++) MMA(o[nt], wla[kc], vf[nt * 2], vf[nt * 2 + 1]);
            #pragma unroll
            for (int p = 0; p < 4; p++) {
                int chunk = 2 * p + (sel >> 1);
                uint32_t a = sb + VL_O + (uint32_t)(keyv * 128 + ((chunk ^ rr) << 4));
                LDSM4T(&vf[p * 4], a);
            }
            #pragma unroll
            for (int nt = 0; nt < 8; nt++) MMA(o[nt], wha[kc], vf[nt * 2], vf[nt * 2 + 1]);
        }
    }

    // ---- write output: per-thread 2 rows x 16 cols as float2 ----
    {
        float* r0p = og + (size_t)wr0 * DH;
        float* r1p = og + (size_t)(wr0 + 8) * DH;
        #pragma unroll
        for (int nt = 0; nt < 8; nt++) {
            *(float2*)(r0p + nt * 8 + 2 * q4) = make_float2(o[nt][0], o[nt][1]);
            *(float2*)(r1p + nt * 8 + 2 * q4) = make_float2(o[nt][2], o[nt][3]);
        }
    }
}

extern "C" void kernel_launch(void* const* d_in, const int* in_sizes, int n_in,
                              void* d_out, int out_size) {
    const float* q = (const float*)d_in[0];
    const float* k = (const float*)d_in[1];
    const float* v = (const float*)d_in[2];
    float* out = (float*)d_out;
    (void)in_sizes; (void)n_in; (void)out_size;

    cudaFuncSetAttribute(sb_mma, cudaFuncAttributeMaxDynamicSharedMemorySize, SM_TOTAL);
    sb_mma<<<NQB * 32, THREADS, SM_TOTAL>>>(q, k, v, out);  // 512 CTAs, heaviest first
}

// round 11
// speedup vs baseline: 1.4585x; 1.4585x over previous
#include <cuda_runtime.h>
#include <cuda_fp16.h>
#include <cstdint>

// Stickbreaking attention via mma.sync (HMMA) fp16-split. B=2 H=16 S=1024 D=64.
// Linear domain: z = sigmoid(x), beta = 1-z; w[i,k] = z_ik*beta_ik*prod_{k<j<=i} beta_ij.
// Key blocks streamed descending, multiplicative carry P per row.
// QK: 3 passes (qh*kh, ql*kh, qh*kl), fp16 splits (residual ~2^-22).
// PV: 2 passes (Wh*V, Wl*V) with V single fp16 (err 2^-11 -> out rel ~1e-4).

#define SEQ 1024
#define DH 64
#define BQ 64
#define BK 64
#define THREADS 128
#define NQB (SEQ / BQ)
#define FULL 0xffffffffu

#define KH_OFF 0
#define KL_OFF 8192
#define VH_OFF 16384

__device__ __forceinline__ uint32_t smem_u32(const void* p) {
    uint32_t a;
    asm("{ .reg .u64 t; cvta.to.shared.u64 t, %1; cvt.u32.u64 %0, t; }" : "=r"(a) : "l"(p));
    return a;
}
__device__ __forceinline__ float ex2f(float x) {
    float r; asm("ex2.approx.f32 %0, %1;" : "=f"(r) : "f"(x)); return r;
}
__device__ __forceinline__ float rcpf(float x) {
    float r; asm("rcp.approx.f32 %0, %1;" : "=f"(r) : "f"(x)); return r;
}

#define MMA(d, a, b0, b1) \
    asm volatile("mma.sync.aligned.m16n8k16.row.col.f32.f16.f16.f32 " \
        "{%0,%1,%2,%3}, {%4,%5,%6,%7}, {%8,%9}, {%0,%1,%2,%3};" \
        : "+f"((d)[0]), "+f"((d)[1]), "+f"((d)[2]), "+f"((d)[3]) \
        : "r"((a)[0]), "r"((a)[1]), "r"((a)[2]), "r"((a)[3]), "r"(b0), "r"(b1))

#define LDSM4(r, addr) \
    asm volatile("ldmatrix.sync.aligned.m8n8.x4.shared.b16 {%0,%1,%2,%3}, [%4];" \
        : "=r"((r)[0]), "=r"((r)[1]), "=r"((r)[2]), "=r"((r)[3]) : "r"(addr))

#define LDSM4T(r, addr) \
    asm volatile("ldmatrix.sync.aligned.m8n8.x4.trans.shared.b16 {%0,%1,%2,%3}, [%4];" \
        : "=r"((r)[0]), "=r"((r)[1]), "=r"((r)[2]), "=r"((r)[3]) : "r"(addr))

__device__ __forceinline__ uint32_t pack2(__half lo, __half hi) {
    __half2 t(lo, hi);
    return *reinterpret_cast<uint32_t*>(&t);
}
__device__ __forceinline__ void split2(float x, __half& h, __half& l) {
    h = __float2half_rn(x);
    l = __float2half_rn(x - __half2float(h));
}

__global__ __launch_bounds__(THREADS)
void sb_mma(const float* __restrict__ q, const float* __restrict__ k,
            const float* __restrict__ v, float* __restrict__ out) {
    __shared__ __align__(16) char smem[24576];
    const uint32_t sb = smem_u32(smem);
    const int tid = threadIdx.x;
    const int lane = tid & 31, warp = tid >> 5;
    const int q4 = lane & 3;                     // quad col idx
    const int sel = lane >> 3, rr = lane & 7;    // ldmatrix select / row

    const int idx = blockIdx.x;
    const int qb = (NQB - 1) - (idx >> 5);       // heaviest q-tiles first
    const int bh = idx & 31;
    const int qbase = qb * BQ;

    const float* qg = q + (size_t)bh * SEQ * DH;
    const float* kg = k + (size_t)bh * SEQ * DH;
    const float* vg = v + (size_t)bh * SEQ * DH;
    float* og = out + (size_t)bh * SEQ * DH;

    // ---- stage Q tile (fp16 hi/lo) into KH/KL buffers, XOR-swizzled ----
    {
        const float4* gq = (const float4*)(qg + (size_t)qbase * DH);
        #pragma unroll
        for (int i = 0; i < 8; i++) {
            int f = i * THREADS + tid;
            int row = f >> 4, c4 = f & 15;
            float4 x = gq[f];
            __half h0, h1, h2, h3, l0, l1, l2, l3;
            split2(x.x, h0, l0); split2(x.y, h1, l1);
            split2(x.z, h2, l2); split2(x.w, h3, l3);
            uint32_t off = (uint32_t)(row * 128 + (((c4 >> 1) ^ (row & 7)) << 4) + (c4 & 1) * 8);
            *(uint2*)(smem + KH_OFF + off) = make_uint2(pack2(h0, h1), pack2(h2, h3));
            *(uint2*)(smem + KL_OFF + off) = make_uint2(pack2(l0, l1), pack2(l2, l3));
        }
    }
    __syncthreads();

    // ---- persistent Q A-fragments (hi & lo), 4 k-chunks ----
    uint32_t qh[4][4], ql[4][4];
    {
        int row = warp * 16 + (sel & 1) * 8 + rr;
        #pragma unroll
        for (int kc = 0; kc < 4; kc++) {
            int chunk = 2 * kc + (sel >> 1);
            uint32_t a = sb + (uint32_t)(row * 128 + ((chunk ^ rr) << 4));
            LDSM4(qh[kc], a + KH_OFF);
            LDSM4(ql[kc], a + KL_OFF);
        }
    }

    float o[8][4];
    #pragma unroll
    for (int nt = 0; nt < 8; nt++) { o[nt][0] = o[nt][1] = o[nt][2] = o[nt][3] = 0.f; }
    float P0 = 1.f, P1 = 1.f;                    // multiplicative carries
    const int wr0 = qbase + warp * 16 + (lane >> 2);
    const float SC = 0.18033688f;                // 0.125 * log2(e)

    // ---- preload first K/V block into registers ----
    float4 kr[8], vr[8];
    {
        const float4* gk = (const float4*)(kg + (size_t)(qb * BK) * DH);
        const float4* gv = (const float4*)(vg + (size_t)(qb * BK) * DH);
        #pragma unroll
        for (int i = 0; i < 8; i++) {
            int f = i * THREADS + tid;
            kr[i] = gk[f]; vr[i] = gv[f];
        }
    }

    #pragma unroll 1
    for (int kb = qb; kb >= 0; --kb) {
        const int kbase = kb * BK;

        __syncthreads();   // prev iteration's smem reads (ldmatrix) done
        // -- convert/store current K (hi/lo) + V (single fp16) --
        #pragma unroll
        for (int i = 0; i < 8; i++) {
            int f = i * THREADS + tid;
            int row = f >> 4, c4 = f & 15;
            uint32_t off = (uint32_t)(row * 128 + (((c4 >> 1) ^ (row & 7)) << 4) + (c4 & 1) * 8);
            __half h0, h1, h2, h3, l0, l1, l2, l3;
            split2(kr[i].x, h0, l0); split2(kr[i].y, h1, l1);
            split2(kr[i].z, h2, l2); split2(kr[i].w, h3, l3);
            *(uint2*)(smem + KH_OFF + off) = make_uint2(pack2(h0, h1), pack2(h2, h3));
            *(uint2*)(smem + KL_OFF + off) = make_uint2(pack2(l0, l1), pack2(l2, l3));
            __half v0 = __float2half_rn(vr[i].x), v1 = __float2half_rn(vr[i].y);
            __half v2 = __float2half_rn(vr[i].z), v3 = __float2half_rn(vr[i].w);
            *(uint2*)(smem + VH_OFF + off) = make_uint2(pack2(v0, v1), pack2(v2, v3));
        }
        __syncthreads();   // K/V visible to all warps

        // -- issue next block's LDGs now: latency covered by QK+scan+PV --
        if (kb > 0) {
            const float4* gk = (const float4*)(kg + (size_t)(kbase - BK) * DH);
            const float4* gv = (const float4*)(vg + (size_t)(kbase - BK) * DH);
            #pragma unroll
            for (int i = 0; i < 8; i++) {
                int f = i * THREADS + tid;
                kr[i] = gk[f]; vr[i] = gv[f];
            }
        }

        // ---- QK^T: D[16 rows x 64 keys], 3 split passes ----
        float d[8][4];
        #pragma unroll
        for (int nt = 0; nt < 8; nt++) { d[nt][0] = d[nt][1] = d[nt][2] = d[nt][3] = 0.f; }

        #pragma unroll
        for (int kc = 0; kc < 4; kc++) {
            uint32_t kf[16];
            const int keyl = (sel >> 1) * 8 + rr;
            const int chunk = 2 * kc + (sel & 1);
            #pragma unroll
            for (int p = 0; p < 4; p++) {
                uint32_t a = sb + KH_OFF + (uint32_t)((p * 16 + keyl) * 128 + ((chunk ^ rr) << 4));
                LDSM4(&kf[p * 4], a);
            }
            #pragma unroll
            for (int nt = 0; nt < 8; nt++) MMA(d[nt], qh[kc], kf[nt * 2], kf[nt * 2 + 1]);
            #pragma unroll
            for (int nt = 0; nt < 8; nt++) MMA(d[nt], ql[kc], kf[nt * 2], kf[nt * 2 + 1]);
            #pragma unroll
            for (int p = 0; p < 4; p++) {
                uint32_t a = sb + KL_OFF + (uint32_t)((p * 16 + keyl) * 128 + ((chunk ^ rr) << 4));
                LDSM4(&kf[p * 4], a);
            }
            #pragma unroll
            for (int nt = 0; nt < 8; nt++) MMA(d[nt], qh[kc], kf[nt * 2], kf[nt * 2 + 1]);
        }

        // ---- stickbreaking scan: linear domain, suffix product over quad ----
        uint32_t wha[4][4], wla[4][4];
        const bool diag = (kb == qb);
        #pragma unroll
        for (int nt = 7; nt >= 0; --nt) {
            const int keyA = kbase + nt * 8 + 2 * q4;
            #pragma unroll
            for (int rs = 0; rs < 2; rs++) {
                float x2a = d[nt][rs * 2 + 0] * SC;
                float x2b = d[nt][rs * 2 + 1] * SC;
                float ta = ex2f(-x2a), tb = ex2f(-x2b);
                float za = rcpf(1.f + ta), zb = rcpf(1.f + tb);
                float ba = 1.f - za, bb = 1.f - zb;
                if (diag) {
                    const int rowg = wr0 + rs * 8;
                    if (keyA > rowg)     { za = 0.f; ba = 1.f; }
                    if (keyA + 1 > rowg) { zb = 0.f; bb = 1.f; }
                }
                float pp = ba * bb;
                float u = pp;                               // inclusive suffix product
                float t1 = __shfl_down_sync(FULL, u, 1, 4);
                u = (q4 < 3) ? u * t1 : u;
                float t2 = __shfl_down_sync(FULL, u, 2, 4);
                u = (q4 < 2) ? u * t2 : u;
                float ue = __shfl_down_sync(FULL, u, 1, 4); // exclusive (lanes above)
                ue = (q4 < 3) ? ue : 1.f;
                float tot = __shfl_sync(FULL, u, 0, 4);
                float& P = rs ? P1 : P0;
                float R  = P * ue;                          // betas of all higher keys
                float Rb = bb * R;
                float wb = zb * Rb;
                float Ra = ba * Rb;
                float wa = za * Ra;
                P *= tot;
                __half ah, al, bh2, bl2;
                split2(wa, ah, al); split2(wb, bh2, bl2);
                wha[nt >> 1][(nt & 1) * 2 + rs] = pack2(ah, bh2);
                wla[nt >> 1][(nt & 1) * 2 + rs] = pack2(al, bl2);
            }
        }

        // ---- PV: O += (Wh + Wl) * V (V single fp16, ldmatrix.trans), 2 passes ----
        #pragma unroll
        for (int kc = 0; kc < 4; kc++) {
            uint32_t vf[16];
            const int keyv = kc * 16 + (sel & 1) * 8 + rr;
            #pragma unroll
            for (int p = 0; p < 4; p++) {
                int chunk = 2 * p + (sel >> 1);
                uint32_t a = sb + VH_OFF + (uint32_t)(keyv * 128 + ((chunk ^ rr) << 4));
                LDSM4T(&vf[p * 4], a);
            }
            #pragma unroll
            for (int nt = 0; nt < 8; nt++) MMA(o[nt], wha[kc], vf[nt * 2], vf[nt * 2 + 1]);
            #pragma unroll
            for (int nt = 0; nt < 8; nt++) MMA(o[nt], wla[kc], vf[nt * 2], vf[nt * 2 + 1]);
        }
    }

    // ---- write output: per-thread 2 rows x 16 cols as float2 ----
    {
        float* r0p = og + (size_t)wr0 * DH;
        float* r1p = og + (size_t)(wr0 + 8) * DH;
        #pragma unroll
        for (int nt = 0; nt < 8; nt++) {
            *(float2*)(r0p + nt * 8 + 2 * q4) = make_float2(o[nt][0], o[nt][1]);
            *(float2*)(r1p + nt * 8 + 2 * q4) = make_float2(o[nt][2], o[nt][3]);
        }
    }
}

extern "C" void kernel_launch(void* const* d_in, const int* in_sizes, int n_in,
                              void* d_out, int out_size) {
    const float* q = (const float*)d_in[0];
    const float* k = (const float*)d_in[1];
    const float* v = (const float*)d_in[2];
    float* out = (float*)d_out;
    (void)in_sizes; (void)n_in; (void)out_size;

    sb_mma<<<NQB * 32, THREADS>>>(q, k, v, out);  // 512 CTAs, heaviest first
}

// round 12
// speedup vs baseline: 1.5938x; 1.0928x over previous
#include <cuda_runtime.h>
#include <cuda_fp16.h>
#include <cstdint>

// Stickbreaking attention via mma.sync (HMMA) fp16-split. B=2 H=16 S=1024 D=64.
// Linear domain: z = sigmoid(x), beta = 1-z; w[i,k] = z_ik*beta_ik*prod_{k<j<=i} beta_ij.
// Key blocks streamed descending, multiplicative carry P per row.
// QK: 3 passes (qh*kh, ql*kh, qh*kl), fp16 splits (residual ~2^-22) — precision-critical.
// PV: 1 pass, W and V single fp16 (output-level rounding only, ~2e-4 each).

#define SEQ 1024
#define DH 64
#define BQ 64
#define BK 64
#define THREADS 128
#define NQB (SEQ / BQ)
#define FULL 0xffffffffu

#define KH_OFF 0
#define KL_OFF 8192
#define VH_OFF 16384

__device__ __forceinline__ uint32_t smem_u32(const void* p) {
    uint32_t a;
    asm("{ .reg .u64 t; cvta.to.shared.u64 t, %1; cvt.u32.u64 %0, t; }" : "=r"(a) : "l"(p));
    return a;
}
__device__ __forceinline__ float ex2f(float x) {
    float r; asm("ex2.approx.f32 %0, %1;" : "=f"(r) : "f"(x)); return r;
}
__device__ __forceinline__ float rcpf(float x) {
    float r; asm("rcp.approx.f32 %0, %1;" : "=f"(r) : "f"(x)); return r;
}

#define MMA(d, a, b0, b1) \
    asm volatile("mma.sync.aligned.m16n8k16.row.col.f32.f16.f16.f32 " \
        "{%0,%1,%2,%3}, {%4,%5,%6,%7}, {%8,%9}, {%0,%1,%2,%3};" \
        : "+f"((d)[0]), "+f"((d)[1]), "+f"((d)[2]), "+f"((d)[3]) \
        : "r"((a)[0]), "r"((a)[1]), "r"((a)[2]), "r"((a)[3]), "r"(b0), "r"(b1))

#define LDSM4(r, addr) \
    asm volatile("ldmatrix.sync.aligned.m8n8.x4.shared.b16 {%0,%1,%2,%3}, [%4];" \
        : "=r"((r)[0]), "=r"((r)[1]), "=r"((r)[2]), "=r"((r)[3]) : "r"(addr))

#define LDSM4T(r, addr) \
    asm volatile("ldmatrix.sync.aligned.m8n8.x4.trans.shared.b16 {%0,%1,%2,%3}, [%4];" \
        : "=r"((r)[0]), "=r"((r)[1]), "=r"((r)[2]), "=r"((r)[3]) : "r"(addr))

__device__ __forceinline__ uint32_t pack2(__half lo, __half hi) {
    __half2 t(lo, hi);
    return *reinterpret_cast<uint32_t*>(&t);
}
__device__ __forceinline__ void split2(float x, __half& h, __half& l) {
    h = __float2half_rn(x);
    l = __float2half_rn(x - __half2float(h));
}

__global__ __launch_bounds__(THREADS)
void sb_mma(const float* __restrict__ q, const float* __restrict__ k,
            const float* __restrict__ v, float* __restrict__ out) {
    __shared__ __align__(16) char smem[24576];
    const uint32_t sb = smem_u32(smem);
    const int tid = threadIdx.x;
    const int lane = tid & 31, warp = tid >> 5;
    const int q4 = lane & 3;                     // quad col idx
    const int sel = lane >> 3, rr = lane & 7;    // ldmatrix select / row

    const int idx = blockIdx.x;
    const int qb = (NQB - 1) - (idx >> 5);       // heaviest q-tiles first
    const int bh = idx & 31;
    const int qbase = qb * BQ;

    const float* qg = q + (size_t)bh * SEQ * DH;
    const float* kg = k + (size_t)bh * SEQ * DH;
    const float* vg = v + (size_t)bh * SEQ * DH;
    float* og = out + (size_t)bh * SEQ * DH;

    // ---- stage Q tile (fp16 hi/lo) into KH/KL buffers, XOR-swizzled ----
    {
        const float4* gq = (const float4*)(qg + (size_t)qbase * DH);
        #pragma unroll
        for (int i = 0; i < 8; i++) {
            int f = i * THREADS + tid;
            int row = f >> 4, c4 = f & 15;
            float4 x = gq[f];
            __half h0, h1, h2, h3, l0, l1, l2, l3;
            split2(x.x, h0, l0); split2(x.y, h1, l1);
            split2(x.z, h2, l2); split2(x.w, h3, l3);
            uint32_t off = (uint32_t)(row * 128 + (((c4 >> 1) ^ (row & 7)) << 4) + (c4 & 1) * 8);
            *(uint2*)(smem + KH_OFF + off) = make_uint2(pack2(h0, h1), pack2(h2, h3));
            *(uint2*)(smem + KL_OFF + off) = make_uint2(pack2(l0, l1), pack2(l2, l3));
        }
    }
    __syncthreads();

    // ---- persistent Q A-fragments (hi & lo), 4 k-chunks ----
    uint32_t qh[4][4], ql[4][4];
    {
        int row = warp * 16 + (sel & 1) * 8 + rr;
        #pragma unroll
        for (int kc = 0; kc < 4; kc++) {
            int chunk = 2 * kc + (sel >> 1);
            uint32_t a = sb + (uint32_t)(row * 128 + ((chunk ^ rr) << 4));
            LDSM4(qh[kc], a + KH_OFF);
            LDSM4(ql[kc], a + KL_OFF);
        }
    }

    float o[8][4];
    #pragma unroll
    for (int nt = 0; nt < 8; nt++) { o[nt][0] = o[nt][1] = o[nt][2] = o[nt][3] = 0.f; }
    float P0 = 1.f, P1 = 1.f;                    // multiplicative carries
    const int wr0 = qbase + warp * 16 + (lane >> 2);
    const float SC = 0.18033688f;                // 0.125 * log2(e)

    // ---- preload first K/V block into registers ----
    float4 kr[8], vr[8];
    {
        const float4* gk = (const float4*)(kg + (size_t)(qb * BK) * DH);
        const float4* gv = (const float4*)(vg + (size_t)(qb * BK) * DH);
        #pragma unroll
        for (int i = 0; i < 8; i++) {
            int f = i * THREADS + tid;
            kr[i] = gk[f]; vr[i] = gv[f];
        }
    }

    #pragma unroll 1
    for (int kb = qb; kb >= 0; --kb) {
        const int kbase = kb * BK;

        __syncthreads();   // prev iteration's smem reads (ldmatrix) done
        // -- convert/store current K (hi/lo) + V (single fp16) --
        #pragma unroll
        for (int i = 0; i < 8; i++) {
            int f = i * THREADS + tid;
            int row = f >> 4, c4 = f & 15;
            uint32_t off = (uint32_t)(row * 128 + (((c4 >> 1) ^ (row & 7)) << 4) + (c4 & 1) * 8);
            __half h0, h1, h2, h3, l0, l1, l2, l3;
            split2(kr[i].x, h0, l0); split2(kr[i].y, h1, l1);
            split2(kr[i].z, h2, l2); split2(kr[i].w, h3, l3);
            *(uint2*)(smem + KH_OFF + off) = make_uint2(pack2(h0, h1), pack2(h2, h3));
            *(uint2*)(smem + KL_OFF + off) = make_uint2(pack2(l0, l1), pack2(l2, l3));
            __half v0 = __float2half_rn(vr[i].x), v1 = __float2half_rn(vr[i].y);
            __half v2 = __float2half_rn(vr[i].z), v3 = __float2half_rn(vr[i].w);
            *(uint2*)(smem + VH_OFF + off) = make_uint2(pack2(v0, v1), pack2(v2, v3));
        }
        __syncthreads();   // K/V visible to all warps

        // -- issue next block's LDGs now: latency covered by QK+scan+PV --
        if (kb > 0) {
            const float4* gk = (const float4*)(kg + (size_t)(kbase - BK) * DH);
            const float4* gv = (const float4*)(vg + (size_t)(kbase - BK) * DH);
            #pragma unroll
            for (int i = 0; i < 8; i++) {
                int f = i * THREADS + tid;
                kr[i] = gk[f]; vr[i] = gv[f];
            }
        }

        // ---- QK^T: D[16 rows x 64 keys], 3 split passes ----
        float d[8][4];
        #pragma unroll
        for (int nt = 0; nt < 8; nt++) { d[nt][0] = d[nt][1] = d[nt][2] = d[nt][3] = 0.f; }

        #pragma unroll
        for (int kc = 0; kc < 4; kc++) {
            uint32_t kf[16];
            const int keyl = (sel >> 1) * 8 + rr;
            const int chunk = 2 * kc + (sel & 1);
            #pragma unroll
            for (int p = 0; p < 4; p++) {
                uint32_t a = sb + KH_OFF + (uint32_t)((p * 16 + keyl) * 128 + ((chunk ^ rr) << 4));
                LDSM4(&kf[p * 4], a);
            }
            #pragma unroll
            for (int nt = 0; nt < 8; nt++) MMA(d[nt], qh[kc], kf[nt * 2], kf[nt * 2 + 1]);
            #pragma unroll
            for (int nt = 0; nt < 8; nt++) MMA(d[nt], ql[kc], kf[nt * 2], kf[nt * 2 + 1]);
            #pragma unroll
            for (int p = 0; p < 4; p++) {
                uint32_t a = sb + KL_OFF + (uint32_t)((p * 16 + keyl) * 128 + ((chunk ^ rr) << 4));
                LDSM4(&kf[p * 4], a);
            }
            #pragma unroll
            for (int nt = 0; nt < 8; nt++) MMA(d[nt], qh[kc], kf[nt * 2], kf[nt * 2 + 1]);
        }

        // ---- stickbreaking scan: linear domain, suffix product over quad ----
        uint32_t wa_[4][4];
        const bool diag = (kb == qb);
        #pragma unroll
        for (int nt = 7; nt >= 0; --nt) {
            const int keyA = kbase + nt * 8 + 2 * q4;
            #pragma unroll
            for (int rs = 0; rs < 2; rs++) {
                float x2a = d[nt][rs * 2 + 0] * SC;
                float x2b = d[nt][rs * 2 + 1] * SC;
                float ta = ex2f(-x2a), tb = ex2f(-x2b);
                float za = rcpf(1.f + ta), zb = rcpf(1.f + tb);
                float ba = 1.f - za, bb = 1.f - zb;
                if (diag) {
                    const int rowg = wr0 + rs * 8;
                    if (keyA > rowg)     { za = 0.f; ba = 1.f; }
                    if (keyA + 1 > rowg) { zb = 0.f; bb = 1.f; }
                }
                float pp = ba * bb;
                float u = pp;                               // inclusive suffix product
                float t1 = __shfl_down_sync(FULL, u, 1, 4);
                u = (q4 < 3) ? u * t1 : u;
                float t2 = __shfl_down_sync(FULL, u, 2, 4);
                u = (q4 < 2) ? u * t2 : u;
                float ue = __shfl_down_sync(FULL, u, 1, 4); // exclusive (lanes above)
                ue = (q4 < 3) ? ue : 1.f;
                float tot = __shfl_sync(FULL, u, 0, 4);
                float& P = rs ? P1 : P0;
                float R  = P * ue;                          // betas of all higher keys
                float Rb = bb * R;
                float wb = zb * Rb;
                float wa = za * ba * Rb;
                P *= tot;
                wa_[nt >> 1][(nt & 1) * 2 + rs] =
                    pack2(__float2half_rn(wa), __float2half_rn(wb));
            }
        }

        // ---- PV: O += W * V (single pass, V via ldmatrix.trans) ----
        #pragma unroll
        for (int kc = 0; kc < 4; kc++) {
            uint32_t vf[16];
            const int keyv = kc * 16 + (sel & 1) * 8 + rr;
            #pragma unroll
            for (int p = 0; p < 4; p++) {
                int chunk = 2 * p + (sel >> 1);
                uint32_t a = sb + VH_OFF + (uint32_t)(keyv * 128 + ((chunk ^ rr) << 4));
                LDSM4T(&vf[p * 4], a);
            }
            #pragma unroll
            for (int nt = 0; nt < 8; nt++) MMA(o[nt], wa_[kc], vf[nt * 2], vf[nt * 2 + 1]);
        }
    }

    // ---- write output: per-thread 2 rows x 16 cols as float2 ----
    {
        float* r0p = og + (size_t)wr0 * DH;
        float* r1p = og + (size_t)(wr0 + 8) * DH;
        #pragma unroll
        for (int nt = 0; nt < 8; nt++) {
            *(float2*)(r0p + nt * 8 + 2 * q4) = make_float2(o[nt][0], o[nt][1]);
            *(float2*)(r1p + nt * 8 + 2 * q4) = make_float2(o[nt][2], o[nt][3]);
        }
    }
}

extern "C" void kernel_launch(void* const* d_in, const int* in_sizes, int n_in,
                              void* d_out, int out_size) {
    const float* q = (const float*)d_in[0];
    const float* k = (const float*)d_in[1];
    const float* v = (const float*)d_in[2];
    float* out = (float*)d_out;
    (void)in_sizes; (void)n_in; (void)out_size;

    sb_mma<<<NQB * 32, THREADS>>>(q, k, v, out);  // 512 CTAs, heaviest first
}